// round 7
// baseline (speedup 1.0000x reference)
#include <cuda_runtime.h>
#include <math.h>
#include <float.h>

#define H 2048
#define S 2048
#define V 50257

// ---------------- device scratch (allocation-free rule) ----------------
__device__ __align__(16) float g_part[148 * H];  // enc column-sum partials
__device__ __align__(16) float g_cat[2 * H];     // [embedded ; attn_applied]
__device__ __align__(16) float g_x[H];           // relu(comb output)
__device__ __align__(16) float g_gh[3 * H];      // w_hh @ h0 dots
__device__ __align__(16) float g_gx[3 * H];      // w_ih @ x dots
__device__ __align__(16) float g_h[H];           // h_new
__device__ __align__(16) float g_logits[V];
__device__ float g_pm[64], g_ps[64];             // partial logsumexp (50 used)

__device__ __forceinline__ float warp_sum(float v) {
    #pragma unroll
    for (int o = 16; o > 0; o >>= 1) v += __shfl_xor_sync(0xffffffffu, v, o);
    return v;
}

// dot of one K=2048 row vs smem vector; 4 passes of 4-deep float4 batches.
__device__ __forceinline__ float dot2048(const float4* __restrict__ wr,
                                         const float4* __restrict__ xs, int lane) {
    float acc = 0.f;
    #pragma unroll
    for (int p = 0; p < 4; ++p) {
        int base = lane + p * 128;
        float4 a0 = wr[base], a1 = wr[base + 32], a2 = wr[base + 64], a3 = wr[base + 96];
        float4 x0 = xs[base], x1 = xs[base + 32], x2 = xs[base + 64], x3 = xs[base + 96];
        acc += a0.x * x0.x + a0.y * x0.y + a0.z * x0.z + a0.w * x0.w;
        acc += a1.x * x1.x + a1.y * x1.y + a1.z * x1.z + a1.w * x1.w;
        acc += a2.x * x2.x + a2.y * x2.y + a2.z * x2.z + a2.w * x2.w;
        acc += a3.x * x3.x + a3.y * x3.y + a3.z * x3.z + a3.w * x3.w;
    }
    return acc;
}

// Generic balanced warp-per-row GEMV body: rows [start, start+cnt), x in smem.
__device__ __forceinline__ void gemv_rows(const float* __restrict__ w,
                                          const float* __restrict__ xs,
                                          float* __restrict__ outv,
                                          int start, int cnt, int wpid, int lane) {
    for (int r = wpid; r < cnt; r += 32) {
        int row = start + r;
        float d = dot2048((const float4*)(w + (size_t)row * H),
                          (const float4*)xs, lane);
        d = warp_sum(d);
        if (lane == 0) outv[row] = d;
    }
}

// K1: gh = w_hh @ h0. grid 148 x 1024; 6144 rows = 76 CTAs x 42 + 72 x 41.
__global__ __launch_bounds__(1024) void k1_whh(const float* __restrict__ w_hh,
                                               const float* __restrict__ hprev) {
    __shared__ __align__(16) float xs[H];
    int tid = threadIdx.x;
    xs[tid] = hprev[tid]; xs[tid + 1024] = hprev[tid + 1024];
    __syncthreads();
    int b = blockIdx.x;
    int start = b * 41 + min(b, 76);
    int cnt = 41 + (b < 76 ? 1 : 0);
    gemv_rows(w_hh, xs, g_gh, start, cnt, tid >> 5, tid & 31);
}

// K2: enc column-sum partials. grid 148 x 1024; 2048 rows = 124x14 + 24x13.
__global__ __launch_bounds__(1024) void k2_enc(const float* __restrict__ enc) {
    int b = blockIdx.x, tid = threadIdx.x;
    int start = b * 13 + min(b, 124);
    int cnt = 13 + (b < 124 ? 1 : 0);
    int c0 = tid, c1 = tid + 1024;
    float s0 = 0.f, s1 = 0.f;
    for (int i = 0; i < cnt; ++i) {
        const float* row = enc + (size_t)(start + i) * H;
        s0 += row[c0]; s1 += row[c1];
    }
    g_part[b * H + c0] = s0;
    g_part[b * H + c1] = s1;
}

// K3: finish column sums -> g_cat[H..2H), embed gather -> g_cat[0..H). 2 blocks.
__global__ void k3_cat(const float* __restrict__ emb,
                       const int* __restrict__ input_id) {
    int col = blockIdx.x * 1024 + threadIdx.x;
    float s = 0.f;
    #pragma unroll 4
    for (int c = 0; c < 148; ++c) s += g_part[c * H + col];
    g_cat[H + col] = s;
    g_cat[col] = emb[(size_t)input_id[0] * H + col];
}

// K4: x = relu(comb_w @ cat + comb_b), K=4096 split across 2 warps/row.
// grid 148 x 1024; 2048 rows = 124x14 + 24x13 (<=14 rows => <=28 warps used).
__global__ __launch_bounds__(1024) void k4_comb(const float* __restrict__ w,
                                                const float* __restrict__ bias) {
    __shared__ __align__(16) float xs[2 * H];
    __shared__ float part[32];
    int tid = threadIdx.x;
    ((float4*)xs)[tid] = ((const float4*)g_cat)[tid];   // 16 KB
    __syncthreads();
    int b = blockIdx.x;
    int start = b * 13 + min(b, 124);
    int cnt = 13 + (b < 124 ? 1 : 0);
    int wpid = tid >> 5, lane = tid & 31;
    int wpair = wpid >> 1, half = wpid & 1;
    if (wpair < cnt) {
        int row = start + wpair;
        float d = dot2048((const float4*)(w + (size_t)row * 2 * H + (size_t)half * H),
                          (const float4*)(xs + half * H), lane);
        d = warp_sum(d);
        if (lane == 0) part[wpid] = d;
    }
    __syncthreads();
    if (tid < cnt) {
        int r = start + tid;
        g_x[r] = fmaxf(part[2 * tid] + part[2 * tid + 1] + bias[r], 0.f);
    }
}

// K5: gx = w_ih @ x. grid 148 x 1024 (same partition as K1).
__global__ __launch_bounds__(1024) void k5_wih(const float* __restrict__ w_ih) {
    __shared__ __align__(16) float xs[H];
    int tid = threadIdx.x;
    xs[tid] = g_x[tid]; xs[tid + 1024] = g_x[tid + 1024];
    __syncthreads();
    int b = blockIdx.x;
    int start = b * 41 + min(b, 76);
    int cnt = 41 + (b < 76 ? 1 : 0);
    gemv_rows(w_ih, xs, g_gx, start, cnt, tid >> 5, tid & 31);
}

// K6: elementwise GRU gates -> g_h. 2 blocks x 1024.
__global__ void k6_gates(const float* __restrict__ b_ih, const float* __restrict__ b_hh,
                         const float* __restrict__ hprev) {
    int j = blockIdx.x * 1024 + threadIdx.x;
    float pre_r = g_gx[j]     + b_ih[j]     + g_gh[j]     + b_hh[j];
    float pre_z = g_gx[H + j] + b_ih[H + j] + g_gh[H + j] + b_hh[H + j];
    float r = 1.f / (1.f + expf(-pre_r));
    float z = 1.f / (1.f + expf(-pre_z));
    float n = tanhf(g_gx[2 * H + j] + b_ih[2 * H + j]
                    + r * (g_gh[2 * H + j] + b_hh[2 * H + j]));
    g_h[j] = (1.f - z) * n + z * hprev[j];
}

// K7: logits = out_w @ h_new + out_b. grid 296 x 1024;
// 50257 rows = 233 CTAs x 170 + 63 x 169, contiguous chunk per CTA.
__global__ __launch_bounds__(1024) void k7_out(const float* __restrict__ w,
                                               const float* __restrict__ bias) {
    __shared__ __align__(16) float xs[H];
    int tid = threadIdx.x;
    xs[tid] = g_h[tid]; xs[tid + 1024] = g_h[tid + 1024];
    __syncthreads();
    int b = blockIdx.x;
    int start = b * 169 + min(b, 233);
    int cnt = 169 + (b < 233 ? 1 : 0);
    int wpid = tid >> 5, lane = tid & 31;
    for (int r = wpid; r < cnt; r += 32) {
        int row = start + r;
        float d = dot2048((const float4*)(w + (size_t)row * H),
                          (const float4*)xs, lane);
        d = warp_sum(d);
        if (lane == 0) g_logits[row] = d + bias[row];
    }
}

// K8: per-block partial (max, sumexp) over 1024-wide slices. 50 blocks.
// Padding uses -FLT_MAX (NOT -inf): -inf pairs produce expf(inf-inf)=NaN.
__global__ void k8_lse_part() {
    __shared__ float sm[1024], ss[1024];
    int tid = threadIdx.x;
    int i = blockIdx.x * 1024 + tid;
    float m = (i < V) ? g_logits[i] : -FLT_MAX;
    float s = (i < V) ? 1.f : 0.f;
    sm[tid] = m; ss[tid] = s;
    __syncthreads();
    for (int o = 512; o > 0; o >>= 1) {
        if (tid < o) {
            float m2 = sm[tid + o], s2 = ss[tid + o];
            float nm = fmaxf(sm[tid], m2);
            ss[tid] = ss[tid] * expf(sm[tid] - nm) + s2 * expf(m2 - nm);
            sm[tid] = nm;
        }
        __syncthreads();
    }
    if (tid == 0) { g_pm[blockIdx.x] = sm[0]; g_ps[blockIdx.x] = ss[0]; }
}

// K9: combine partials (per block, cheap/deterministic) + write all outputs:
// log_probs (V) | h_new (H) | attn_weights=1 (S)
__global__ void k9_write(float* __restrict__ out, int out_size) {
    __shared__ float shift_s;
    if (threadIdx.x == 0) {
        float m = -FLT_MAX, s = 0.f;
        #pragma unroll
        for (int c = 0; c < 50; ++c) {
            float m2 = g_pm[c], s2 = g_ps[c];
            float nm = fmaxf(m, m2);
            s = s * expf(m - nm) + s2 * expf(m2 - nm);
            m = nm;
        }
        shift_s = m + logf(s);
    }
    __syncthreads();
    int i = blockIdx.x * 1024 + threadIdx.x;
    if (i >= out_size) return;
    if (i < V)            out[i] = g_logits[i] - shift_s;
    else if (i < V + H)   out[i] = g_h[i - V];
    else                  out[i] = 1.0f;
}

extern "C" void kernel_launch(void* const* d_in, const int* in_sizes, int n_in,
                              void* d_out, int out_size) {
    const int*   input_id = (const int*)  d_in[0];
    const float* hidden   = (const float*)d_in[1];   // (1,1,H)
    const float* enc      = (const float*)d_in[2];   // (S,H)
    const float* emb      = (const float*)d_in[3];   // (V,H)
    // d_in[4], d_in[5]: attn_w / attn_b — provably dead (softmax over singleton)
    const float* comb_w   = (const float*)d_in[6];
    const float* comb_b   = (const float*)d_in[7];
    const float* w_ih     = (const float*)d_in[8];
    const float* w_hh     = (const float*)d_in[9];
    const float* b_ih     = (const float*)d_in[10];
    const float* b_hh     = (const float*)d_in[11];
    const float* out_w    = (const float*)d_in[12];
    const float* out_b    = (const float*)d_in[13];
    float* out = (float*)d_out;

    k1_whh<<<148, 1024>>>(w_hh, hidden);
    k2_enc<<<148, 1024>>>(enc);
    k3_cat<<<2, 1024>>>(emb, input_id);
    k4_comb<<<148, 1024>>>(comb_w, comb_b);
    k5_wih<<<148, 1024>>>(w_ih);
    k6_gates<<<2, 1024>>>(b_ih, b_hh, hidden);
    k7_out<<<296, 1024>>>(out_w, out_b);
    k8_lse_part<<<50, 1024>>>();
    k9_write<<<(out_size + 1023) / 1024, 1024>>>(out, out_size);
}

// round 9
// speedup vs baseline: 1.1029x; 1.1029x over previous
#include <cuda_runtime.h>
#include <math.h>
#include <float.h>

#define H 2048
#define S 2048
#define V 50257

// ---------------- device scratch (allocation-free rule) ----------------
__device__ __align__(16) float g_part[148 * H];  // enc column-sum partials
__device__ __align__(16) float g_cat[2 * H];     // [embedded ; attn_applied]
__device__ __align__(16) float g_x[H];           // relu(comb output)
__device__ __align__(16) float g_gh[3 * H];      // w_hh @ h0 dots
__device__ __align__(16) float g_gx[3 * H];      // w_ih @ x dots
__device__ __align__(16) float g_h[H];           // h_new
__device__ __align__(16) float g_logits[V];
__device__ float g_pm[64], g_ps[64];             // partial logsumexp (50 used)

__device__ __forceinline__ float warp_sum(float v) {
    #pragma unroll
    for (int o = 16; o > 0; o >>= 1) v += __shfl_xor_sync(0xffffffffu, v, o);
    return v;
}

__device__ __forceinline__ void add4(float4& a, const float4 b) {
    a.x += b.x; a.y += b.y; a.z += b.z; a.w += b.w;
}

// dot of one K=512*PH-float row vs smem vector; PH phases of 8-deep float4 batches.
// PH=2 is EXACTLY the R4 dot2048 that achieved 6.5 TB/s in k6_out.
template <int PH>
__device__ __forceinline__ float dotPH(const float4* __restrict__ wr,
                                       const float4* __restrict__ xs, int lane) {
    float acc = 0.f;
    #pragma unroll
    for (int ph = 0; ph < PH; ++ph) {
        float4 wb[8];
        #pragma unroll
        for (int i = 0; i < 8; ++i) wb[i] = wr[lane + 32 * (ph * 8 + i)];
        #pragma unroll
        for (int i = 0; i < 8; ++i) {
            float4 x = xs[lane + 32 * (ph * 8 + i)];
            acc += wb[i].x * x.x + wb[i].y * x.y + wb[i].z * x.z + wb[i].w * x.w;
        }
    }
    return acc;
}

// kA: fused independent work. grid 298 x 256.
//   b in [0,148)   : gh = w_hh @ h0. 1184 warps, warp-stride rows (5-6 rows/warp).
//   b in [148,296) : enc column-sum partials, 13/14-row chunk, 4 accumulator chains.
//   b in [296,298) : embedding gather -> g_cat[0..H).
__global__ __launch_bounds__(256) void kA_fused(
        const float* __restrict__ w_hh, const float* __restrict__ hprev,
        const float* __restrict__ enc,  const float* __restrict__ emb,
        const int* __restrict__ input_id) {
    __shared__ __align__(16) float xs[H];
    int b = blockIdx.x, tid = threadIdx.x;
    if (b < 148) {
        ((float4*)xs)[tid]       = ((const float4*)hprev)[tid];
        ((float4*)xs)[tid + 256] = ((const float4*)hprev)[tid + 256];
        __syncthreads();
        int g = b * 8 + (tid >> 5), lane = tid & 31;
        for (int row = g; row < 3 * H; row += 1184) {
            float d = warp_sum(dotPH<2>((const float4*)(w_hh + (size_t)row * H),
                                        (const float4*)xs, lane));
            if (lane == 0) g_gh[row] = d;
        }
    } else if (b < 296) {
        int cb = b - 148;
        int start = cb * 13 + min(cb, 124);
        int cnt = 13 + (cb < 124 ? 1 : 0);
        float4 z = make_float4(0.f, 0.f, 0.f, 0.f);
        float4 s0 = z, s1 = z, s2 = z, s3 = z;     // 2-row unroll x 2 col groups
        int i = 0;
        for (; i + 2 <= cnt; i += 2) {
            const float4* r0 = (const float4*)(enc + (size_t)(start + i) * H);
            const float4* r1 = (const float4*)(enc + (size_t)(start + i + 1) * H);
            add4(s0, r0[tid]); add4(s1, r0[tid + 256]);
            add4(s2, r1[tid]); add4(s3, r1[tid + 256]);
        }
        if (i < cnt) {
            const float4* r0 = (const float4*)(enc + (size_t)(start + i) * H);
            add4(s0, r0[tid]); add4(s1, r0[tid + 256]);
        }
        add4(s0, s2); add4(s1, s3);
        ((float4*)(g_part + (size_t)cb * H))[tid]       = s0;
        ((float4*)(g_part + (size_t)cb * H))[tid + 256] = s1;
    } else {
        int idx = (b - 296) * 256 + tid;           // 0..511 float4s
        ((float4*)g_cat)[idx] =
            ((const float4*)(emb + (size_t)input_id[0] * H))[idx];
    }
}

// kB: finish column sums -> g_cat[H..2H). 2 blocks x 1024; 4 accumulator chains.
__global__ void kB_cat() {
    int col = blockIdx.x * 1024 + threadIdx.x;
    float s0 = 0.f, s1 = 0.f, s2 = 0.f, s3 = 0.f;
    for (int c = 0; c < 148; c += 4) {             // 148 = 4*37 exact
        s0 += g_part[(c + 0) * H + col];
        s1 += g_part[(c + 1) * H + col];
        s2 += g_part[(c + 2) * H + col];
        s3 += g_part[(c + 3) * H + col];
    }
    g_cat[H + col] = (s0 + s1) + (s2 + s3);
}

// kC: x = relu(comb_w @ cat + comb_b). Full K=4096 rows (16 KB streams),
// warp-stride rows. grid 148 x 256 (1184 warps, 1-2 rows/warp).
__global__ __launch_bounds__(256) void kC_comb(const float* __restrict__ w,
                                               const float* __restrict__ bias) {
    __shared__ __align__(16) float xs[2 * H];      // 16 KB
    int tid = threadIdx.x;
    #pragma unroll
    for (int i = 0; i < 4; ++i)
        ((float4*)xs)[tid + 256 * i] = ((const float4*)g_cat)[tid + 256 * i];
    __syncthreads();
    int g = blockIdx.x * 8 + (tid >> 5), lane = tid & 31;
    for (int row = g; row < H; row += 1184) {
        float d = warp_sum(dotPH<4>((const float4*)(w + (size_t)row * 2 * H),
                                    (const float4*)xs, lane));
        if (lane == 0) g_x[row] = fmaxf(d + bias[row], 0.f);
    }
}

// kD: gx = w_ih @ x. grid 148 x 256, warp-stride rows (5-6 rows/warp).
__global__ __launch_bounds__(256) void kD_wih(const float* __restrict__ w_ih) {
    __shared__ __align__(16) float xs[H];
    int tid = threadIdx.x;
    ((float4*)xs)[tid]       = ((const float4*)g_x)[tid];
    ((float4*)xs)[tid + 256] = ((const float4*)g_x)[tid + 256];
    __syncthreads();
    int g = blockIdx.x * 8 + (tid >> 5), lane = tid & 31;
    for (int row = g; row < 3 * H; row += 1184) {
        float d = warp_sum(dotPH<2>((const float4*)(w_ih + (size_t)row * H),
                                    (const float4*)xs, lane));
        if (lane == 0) g_gx[row] = d;
    }
}

// kE: elementwise GRU gates -> g_h. 2 blocks x 1024.
__global__ void kE_gates(const float* __restrict__ b_ih, const float* __restrict__ b_hh,
                         const float* __restrict__ hprev) {
    int j = blockIdx.x * 1024 + threadIdx.x;
    float pre_r = g_gx[j]     + b_ih[j]     + g_gh[j]     + b_hh[j];
    float pre_z = g_gx[H + j] + b_ih[H + j] + g_gh[H + j] + b_hh[H + j];
    float r = 1.f / (1.f + expf(-pre_r));
    float z = 1.f / (1.f + expf(-pre_z));
    float n = tanhf(g_gx[2 * H + j] + b_ih[2 * H + j]
                    + r * (g_gh[2 * H + j] + b_hh[2 * H + j]));
    g_h[j] = (1.f - z) * n + z * hprev[j];
}

// kF: logits = out_w @ h_new + out_b. VERBATIM R4 k6_out (measured ~6.5 TB/s):
// grid 296 x 1024, row = wpid*296 + b, stride 9472 (5.3 sequential rows/warp).
__global__ __launch_bounds__(1024) void kF_out(const float* __restrict__ w,
                                               const float* __restrict__ bias) {
    __shared__ __align__(16) float xs[H];
    int tid = threadIdx.x;
    xs[tid] = g_h[tid]; xs[tid + 1024] = g_h[tid + 1024];
    __syncthreads();
    int wpid = tid >> 5, lane = tid & 31;
    for (int row = wpid * 296 + blockIdx.x; row < V; row += 296 * 32) {
        float d = warp_sum(dotPH<2>((const float4*)(w + (size_t)row * H),
                                    (const float4*)xs, lane));
        if (lane == 0) g_logits[row] = d + bias[row];
    }
}

// kG: per-block partial (max, sumexp) over 1024-wide slices. 50 blocks.
// Padding uses -FLT_MAX (NOT -inf: -inf pairs give expf(inf-inf)=NaN).
__global__ void kG_lse_part() {
    __shared__ float sm[1024], ss[1024];
    int tid = threadIdx.x;
    int i = blockIdx.x * 1024 + tid;
    float m = (i < V) ? g_logits[i] : -FLT_MAX;
    float s = (i < V) ? 1.f : 0.f;
    sm[tid] = m; ss[tid] = s;
    __syncthreads();
    for (int o = 512; o > 0; o >>= 1) {
        if (tid < o) {
            float m2 = sm[tid + o], s2 = ss[tid + o];
            float nm = fmaxf(sm[tid], m2);
            ss[tid] = ss[tid] * expf(sm[tid] - nm) + s2 * expf(m2 - nm);
            sm[tid] = nm;
        }
        __syncthreads();
    }
    if (tid == 0) { g_pm[blockIdx.x] = sm[0]; g_ps[blockIdx.x] = ss[0]; }
}

// kH: combine 50 partials with ONE warp. BUGFIX vs R8: a 32-lane warp cannot
// read 50 entries with `lane < 50` — entries 32..49 were dropped. Each lane
// now pre-combines entries lane and lane+32 before the butterfly.
__global__ void kH_write(float* __restrict__ out, int out_size) {
    __shared__ float shift_s;
    if (threadIdx.x < 32) {
        int lane = threadIdx.x;
        float m = g_pm[lane];                      // lane in [0,32) < 50: valid
        float s = g_ps[lane];
        if (lane + 32 < 50) {
            float m2 = g_pm[lane + 32], s2 = g_ps[lane + 32];
            float nm = fmaxf(m, m2);
            s = s * expf(m - nm) + s2 * expf(m2 - nm);
            m = nm;
        }
        #pragma unroll
        for (int o = 16; o > 0; o >>= 1) {
            float m2 = __shfl_xor_sync(0xffffffffu, m, o);
            float s2 = __shfl_xor_sync(0xffffffffu, s, o);
            float nm = fmaxf(m, m2);
            s = s * expf(m - nm) + s2 * expf(m2 - nm);
            m = nm;
        }
        if (lane == 0) shift_s = m + logf(s);
    }
    __syncthreads();
    int i = blockIdx.x * 1024 + threadIdx.x;
    if (i >= out_size) return;
    if (i < V)            out[i] = g_logits[i] - shift_s;
    else if (i < V + H)   out[i] = g_h[i - V];
    else                  out[i] = 1.0f;
}

extern "C" void kernel_launch(void* const* d_in, const int* in_sizes, int n_in,
                              void* d_out, int out_size) {
    const int*   input_id = (const int*)  d_in[0];
    const float* hidden   = (const float*)d_in[1];   // (1,1,H)
    const float* enc      = (const float*)d_in[2];   // (S,H)
    const float* emb      = (const float*)d_in[3];   // (V,H)
    // d_in[4], d_in[5]: attn_w / attn_b — provably dead (softmax over singleton)
    const float* comb_w   = (const float*)d_in[6];
    const float* comb_b   = (const float*)d_in[7];
    const float* w_ih     = (const float*)d_in[8];
    const float* w_hh     = (const float*)d_in[9];
    const float* b_ih     = (const float*)d_in[10];
    const float* b_hh     = (const float*)d_in[11];
    const float* out_w    = (const float*)d_in[12];
    const float* out_b    = (const float*)d_in[13];
    float* out = (float*)d_out;

    kA_fused<<<298, 256>>>(w_hh, hidden, enc, emb, input_id);
    kB_cat<<<2, 1024>>>();
    kC_comb<<<148, 256>>>(comb_w, comb_b);
    kD_wih<<<148, 256>>>(w_ih);
    kE_gates<<<2, 1024>>>(b_ih, b_hh, hidden);
    kF_out<<<296, 1024>>>(out_w, out_b);
    kG_lse_part<<<50, 1024>>>();
    kH_write<<<(out_size + 1023) / 1024, 1024>>>(out, out_size);
}

// round 10
// speedup vs baseline: 1.3833x; 1.2543x over previous
#include <cuda_runtime.h>
#include <math.h>
#include <float.h>

#define H 2048
#define S 2048
#define V 50257

// ---------------- device scratch (allocation-free rule) ----------------
__device__ __align__(16) float g_part[64 * H];   // enc column-sum partials
__device__ __align__(16) float g_cat[2 * H];     // [embedded ; attn_applied]
__device__ __align__(16) float g_x[H];           // relu(comb output)
__device__ __align__(16) float g_gh[3 * H];      // w_hh @ h0 dots
__device__ __align__(16) float g_gx[3 * H];      // w_ih @ x dots
__device__ __align__(16) float g_h[H];           // h_new
__device__ __align__(16) float g_logits[V];
__device__ float g_shift;

__device__ __forceinline__ float warp_sum(float v) {
    #pragma unroll
    for (int o = 16; o > 0; o >>= 1) v += __shfl_xor_sync(0xffffffffu, v, o);
    return v;
}

__device__ __forceinline__ float dot_row_warp(const float4* __restrict__ wr,
                                              const float4* __restrict__ xv,
                                              int n4, int lane) {
    float acc = 0.f;
    #pragma unroll 16
    for (int i = lane; i < n4; i += 32) {
        float4 a = wr[i], x = xv[i];
        acc += a.x * x.x + a.y * x.y + a.z * x.z + a.w * x.w;
    }
    return warp_sum(acc);
}

// K=2048 dot, weights via __ldcs (evict-first streaming), x from smem.
// Two phases of 8-deep float4 batches (the R4 k6_out access shape).
__device__ __forceinline__ float dot2048_cs(const float4* __restrict__ wr,
                                            const float4* __restrict__ xs, int lane) {
    float acc = 0.f;
    #pragma unroll
    for (int ph = 0; ph < 2; ++ph) {
        float4 wb[8];
        #pragma unroll
        for (int i = 0; i < 8; ++i) wb[i] = __ldcs(wr + lane + 32 * (ph * 8 + i));
        #pragma unroll
        for (int i = 0; i < 8; ++i) {
            float4 x = xs[lane + 32 * (ph * 8 + i)];
            acc += wb[i].x * x.x + wb[i].y * x.y + wb[i].z * x.z + wb[i].w * x.w;
        }
    }
    return acc;
}

// K1: fused independent work, partitioned by blockIdx.x (1288 blocks x 256 thr):
//   [0, 768)       : gh = w_hh @ h0, warp-per-row (6144 rows)
//   [768, 1280)    : enc column-sum partials (8 col-chunks x 64 row-chunks of 32)
//   [1280, 1288)   : embedding gather -> g_cat[0..H)
__global__ void k1_fused(const float* __restrict__ w_hh,
                         const float* __restrict__ hprev,
                         const float* __restrict__ enc,
                         const float* __restrict__ emb,
                         const int* __restrict__ input_id) {
    int b = blockIdx.x;
    if (b < 768) {
        int warp = threadIdx.x >> 5, lane = threadIdx.x & 31;
        int row = b * 8 + warp;                      // 0..6143
        float d = dot_row_warp((const float4*)(w_hh + (size_t)row * H),
                               (const float4*)hprev, H / 4, lane);
        if (lane == 0) g_gh[row] = d;
    } else if (b < 1280) {
        int cb = b - 768;
        int col = (cb & 7) * 256 + threadIdx.x;
        int rc  = cb >> 3;                           // 0..63
        int r0  = rc * 32;
        float s = 0.f;
        #pragma unroll
        for (int i = 0; i < 32; ++i)
            s += enc[(size_t)(r0 + i) * H + col];
        g_part[rc * H + col] = s;
    } else {
        int j = (b - 1280) * 256 + threadIdx.x;      // 0..2047
        g_cat[j] = emb[(size_t)input_id[0] * H + j];
    }
}

// K2: finish column sums -> g_cat[H..2H)
__global__ void k2_finish_cat() {
    int j = blockIdx.x * 256 + threadIdx.x;
    float s = 0.f;
    #pragma unroll
    for (int c = 0; c < 64; ++c) s += g_part[c * H + j];
    g_cat[H + j] = s;
}

// K3: x = relu(comb_w @ cat + comb_b). warp-per-row, full-unroll 32.
__global__ void k3_comb(const float* __restrict__ w, const float* __restrict__ b) {
    int warp = threadIdx.x >> 5, lane = threadIdx.x & 31;
    int row = blockIdx.x * 8 + warp;                 // 2048 rows
    const float4* wr = (const float4*)(w + (size_t)row * 2 * H);
    const float4* cv = (const float4*)g_cat;
    float acc = 0.f;
    #pragma unroll
    for (int i = lane; i < (2 * H) / 4; i += 32) {
        float4 a = wr[i], x = cv[i];
        acc += a.x * x.x + a.y * x.y + a.z * x.z + a.w * x.w;
    }
    acc = warp_sum(acc);
    if (lane == 0) g_x[row] = fmaxf(acc + b[row], 0.f);
}

// K4: gx = w_ih @ x. k6-shaped: grid 148 x 1024, row = wpid*148 + b,
// stride 4736, smem x, __ldcs weights. 6144 rows -> 1-2 rows/warp.
__global__ __launch_bounds__(1024) void k4_wih(const float* __restrict__ w_ih) {
    __shared__ __align__(16) float xs[H];
    int tid = threadIdx.x;
    ((float4*)xs)[tid % 512] = ((const float4*)g_x)[tid % 512]; // 512 float4s, 2x redundant
    __syncthreads();
    int wpid = tid >> 5, lane = tid & 31;
    for (int row = wpid * 148 + blockIdx.x; row < 3 * H; row += 4736) {
        float d = warp_sum(dot2048_cs((const float4*)(w_ih + (size_t)row * H),
                                      (const float4*)xs, lane));
        if (lane == 0) g_gx[row] = d;
    }
}

// K5: elementwise GRU gates -> g_h. 8 blocks x 256.
__global__ void k5_gates(const float* __restrict__ b_ih, const float* __restrict__ b_hh,
                         const float* __restrict__ hprev) {
    int j = blockIdx.x * 256 + threadIdx.x;
    float pre_r = g_gx[j]     + b_ih[j]     + g_gh[j]     + b_hh[j];
    float pre_z = g_gx[H + j] + b_ih[H + j] + g_gh[H + j] + b_hh[H + j];
    float r = 1.f / (1.f + expf(-pre_r));
    float z = 1.f / (1.f + expf(-pre_z));
    float n = tanhf(g_gx[2 * H + j] + b_ih[2 * H + j]
                    + r * (g_gh[2 * H + j] + b_hh[2 * H + j]));
    g_h[j] = (1.f - z) * n + z * hprev[j];
}

// K6: logits = out_w @ h_new + out_b. Single wave: grid 148 x 1024,
// row = wpid*148 + b, stride 4736 (10.6 rows/warp, dense global footprint).
__global__ __launch_bounds__(1024) void k6_out(const float* __restrict__ w,
                                               const float* __restrict__ bias) {
    __shared__ __align__(16) float xs[H];
    int tid = threadIdx.x;
    ((float4*)xs)[tid % 512] = ((const float4*)g_h)[tid % 512];
    __syncthreads();
    int wpid = tid >> 5, lane = tid & 31;
    for (int row = wpid * 148 + blockIdx.x; row < V; row += 4736) {
        float d = warp_sum(dot2048_cs((const float4*)(w + (size_t)row * H),
                                      (const float4*)xs, lane));
        if (lane == 0) g_logits[row] = d + bias[row];
    }
}

// K7: single-block online logsumexp over g_logits -> g_shift.
__global__ void k7_lse() {
    __shared__ float sm[1024], ss[1024];
    int tid = threadIdx.x;
    float m = -FLT_MAX, s = 0.f;
    for (int i = tid; i < V; i += 1024) {
        float l = g_logits[i];
        float nm = fmaxf(m, l);
        s = s * expf(m - nm) + expf(l - nm);
        m = nm;
    }
    sm[tid] = m; ss[tid] = s;
    __syncthreads();
    for (int o = 512; o > 0; o >>= 1) {
        if (tid < o) {
            float m2 = sm[tid + o], s2 = ss[tid + o];
            float nm = fmaxf(sm[tid], m2);
            ss[tid] = ss[tid] * expf(sm[tid] - nm) + s2 * expf(m2 - nm);
            sm[tid] = nm;
        }
        __syncthreads();
    }
    if (tid == 0) g_shift = sm[0] + logf(ss[0]);
}

// K8: write outputs: log_probs (V) | h_new (H) | attn_weights=1 (S)
__global__ void k8_write(float* __restrict__ out, int out_size) {
    int i = blockIdx.x * 256 + threadIdx.x;
    if (i >= out_size) return;
    if (i < V)            out[i] = g_logits[i] - g_shift;
    else if (i < V + H)   out[i] = g_h[i - V];
    else                  out[i] = 1.0f;
}

extern "C" void kernel_launch(void* const* d_in, const int* in_sizes, int n_in,
                              void* d_out, int out_size) {
    const int*   input_id = (const int*)  d_in[0];
    const float* hidden   = (const float*)d_in[1];   // (1,1,H)
    const float* enc      = (const float*)d_in[2];   // (S,H)
    const float* emb      = (const float*)d_in[3];   // (V,H)
    // d_in[4], d_in[5]: attn_w / attn_b — provably dead (softmax over singleton)
    const float* comb_w   = (const float*)d_in[6];
    const float* comb_b   = (const float*)d_in[7];
    const float* w_ih     = (const float*)d_in[8];
    const float* w_hh     = (const float*)d_in[9];
    const float* b_ih     = (const float*)d_in[10];
    const float* b_hh     = (const float*)d_in[11];
    const float* out_w    = (const float*)d_in[12];
    const float* out_b    = (const float*)d_in[13];
    float* out = (float*)d_out;

    k1_fused<<<1288, 256>>>(w_hh, hidden, enc, emb, input_id);
    k2_finish_cat<<<H / 256, 256>>>();
    k3_comb<<<H / 8, 256>>>(comb_w, comb_b);
    k4_wih<<<148, 1024>>>(w_ih);
    k5_gates<<<H / 256, 256>>>(b_ih, b_hh, hidden);
    k6_out<<<148, 1024>>>(out_w, out_b);
    k7_lse<<<1, 1024>>>();
    k8_write<<<(out_size + 255) / 256, 256>>>(out, out_size);
}